// round 12
// baseline (speedup 1.0000x reference)
#include <cuda_runtime.h>
#include <cuda_bf16.h>
#include <math.h>

// RingDilatedAttentionRefactored: B=1, N=32768, H=16, D=64.
// Causal collapse (derived R1, rel_err=0 across all rounds):
//   out[rows   0..127] = v[rows 0..127]
//   out[rows 128..255] = v[rows 0..127]
//   out[rows 256..   ] = 0
// R11 probe: 512 threads / 2 rows per block (grid 16384). Same winning shape
// as R2/R8 (one STG.128 .cs per thread, contiguous in-order sweep), halved
// block count. Wall time is pinned at the DRAM write drain (~134 MB/replay
// @ ~5.9 TB/s sustained); this isolates block-count overhead at the margin.
// Inputs (metadata order): q (f32), k (f32), v (f32), is_causal (i32).

#define HD        1024                   // H*D floats per row
#define NTHREADS  512
#define NBLK      16384                  // 2 rows per block
#define COPY_BLKS 128                    // blocks covering rows 0..255
#define V4MASK    32767u                 // wrap to v rows 0..127 (float4 units)

__device__ __forceinline__ void stcs4(float4* p, float4 v) {
    __stcs(p, v);
}

__global__ void __launch_bounds__(NTHREADS)
fused_dilated_attn_kernel(const float* __restrict__ q,
                          const float* __restrict__ k,
                          const float* __restrict__ v,
                          const int*   __restrict__ is_causal,
                          float*       __restrict__ out)
{
    const int b   = blockIdx.x;
    const int tid = threadIdx.x;
    const unsigned idx4 = (unsigned)b * NTHREADS + tid;   // global float4 index
    float4* __restrict__ out4 = reinterpret_cast<float4*>(out);

    if (b >= COPY_BLKS) {
        // zero region (rows 256..32767): is_causal irrelevant — segments only
        // cover rows 0..255, the rest is zero either way
        stcs4(out4 + idx4, make_float4(0.f, 0.f, 0.f, 0.f));
        return;
    }

    // Only the first 128 blocks touch the flag (uniform, L2-broadcast).
    if (__ldg(is_causal) != 0) {
        // copy region: out float4 idx4 = v float4 (idx4 mod 32768)
        stcs4(out4 + idx4,
              __ldg(reinterpret_cast<const float4*>(v) + (idx4 & V4MASK)));
        return;
    }

    // ---- non-causal fallback (never exercised by setup_inputs) ----
    // Block b < 128 owns rows 2b, 2b+1. 16 warps: warp w -> row 2b+(w>>3),
    // heads (w&7)*2 .. +1. Warp-cooperative softmax-attention, 128 keys, D=64.
    const int wid  = tid >> 5;
    const int lane = tid & 31;
    const int r    = 2 * b + (wid >> 3);
    const int qi   = r & 127;
    const int step = 128 << (r >> 7);       // 128 or 256
    const float scale = 0.125f;             // 1/sqrt(64)

    #pragma unroll
    for (int hh = 0; hh < 2; hh++) {
        const int h = (wid & 7) * 2 + hh;
        const float* qp = q + (size_t)r * HD + h * 64;
        const float q0 = qp[lane];
        const float q1 = qp[lane + 32];

        // distributed scores: lane l keeps score j where (j & 31) == l
        float sc[4];
        for (int j = 0; j < 128; j++) {
            const int pos = qi + step * j;
            const float* kp = k + (size_t)pos * HD + h * 64;
            float p = q0 * kp[lane] + q1 * kp[lane + 32];
            #pragma unroll
            for (int off = 16; off >= 1; off >>= 1)
                p += __shfl_xor_sync(0xFFFFFFFFu, p, off);
            if ((j & 31) == lane) sc[j >> 5] = p * scale;
        }

        float m = fmaxf(fmaxf(sc[0], sc[1]), fmaxf(sc[2], sc[3]));
        #pragma unroll
        for (int off = 16; off >= 1; off >>= 1)
            m = fmaxf(m, __shfl_xor_sync(0xFFFFFFFFu, m, off));
        float e[4], lsum = 0.f;
        #pragma unroll
        for (int jj = 0; jj < 4; jj++) { e[jj] = __expf(sc[jj] - m); lsum += e[jj]; }
        #pragma unroll
        for (int off = 16; off >= 1; off >>= 1)
            lsum += __shfl_xor_sync(0xFFFFFFFFu, lsum, off);
        const float inv = 1.f / lsum;

        float acc0 = 0.f, acc1 = 0.f;
        for (int j = 0; j < 128; j++) {
            const float w = __shfl_sync(0xFFFFFFFFu, e[j >> 5], j & 31) * inv;
            const int pos = qi + step * j;
            const float* vp = v + (size_t)pos * HD + h * 64;
            acc0 += w * vp[lane];
            acc1 += w * vp[lane + 32];
        }

        float* op = out + (size_t)r * HD + h * 64;
        op[lane]      = acc0;
        op[lane + 32] = acc1;
    }
}

extern "C" void kernel_launch(void* const* d_in, const int* in_sizes, int n_in,
                              void* d_out, int out_size)
{
    const float* q = (const float*)d_in[0];
    const float* k = (const float*)d_in[1];
    const float* v = (const float*)d_in[2];
    const int* is_causal = (const int*)d_in[3];
    float* out = (float*)d_out;

    fused_dilated_attn_kernel<<<NBLK, NTHREADS>>>(q, k, v, is_causal, out);
}

// round 13
// speedup vs baseline: 1.0283x; 1.0283x over previous
#include <cuda_runtime.h>
#include <cuda_bf16.h>
#include <math.h>

// RingDilatedAttentionRefactored: B=1, N=32768, H=16, D=64.
// Segments [128 (dil 1), 128 (dil 2)]. Under the causal mask only the j=0
// (diagonal) key survives in both segments; softmax with NEG_INF=-1e30 is an
// exact one-hot in fp32:
//   out[rows   0..127] = v[rows 0..127]
//   out[rows 128..255] = v[rows 0..127]
//   out[rows 256..   ] = 0
// FINAL (measured best, 22.56us): one block per output row, 256 threads, one
// STG.128 (.cs) per thread, in-order contiguous sweep. Wall time is pinned at
// the DRAM write drain: 134 MB/replay at ~5.9 TB/s sustained write (~72% of
// the 8 TB/s bidirectional spec). Exhausted-and-flat alternatives: persistent
// grid (R3, +2us), write-back stores (R4, +0.3us), STG.256 + L2 evict_last
// (R7, neutral — persisting hints demoted without the carveout, which the
// harness device-limit guard forbids), 512-thr/2-row blocks (R11, neutral).
// Traffic reduction is closed: footprint (134MB) > L2 (126MB) guarantees
// sweep thrash; cross-replay skip violates determinism rules.
// Inputs (metadata order): q (f32), k (f32), v (f32), is_causal (i32).

#define HD      1024                    // H*D floats per row
#define ROW4    256                     // float4 per row
#define N_ROWS  32768
#define GRID    (N_ROWS)                // one block per output row

__device__ __forceinline__ void stcs4(float4* p, float4 v) {
    __stcs(p, v);
}

__global__ void __launch_bounds__(256)
fused_dilated_attn_kernel(const float* __restrict__ q,
                          const float* __restrict__ k,
                          const float* __restrict__ v,
                          const int*   __restrict__ is_causal,
                          float*       __restrict__ out)
{
    const int b   = blockIdx.x;
    const int tid = threadIdx.x;
    float4* __restrict__ out4 = reinterpret_cast<float4*>(out) + (size_t)b * ROW4;

    if (b >= 256) {
        // zero tail: rows 256..32767 (99.2% of output; is_causal irrelevant —
        // the two segments only cover rows 0..255, the rest is zero either way)
        stcs4(out4 + tid, make_float4(0.f, 0.f, 0.f, 0.f));
        return;
    }

    // Only the first 256 blocks touch the flag (uniform, L2-broadcast).
    if (__ldg(is_causal) != 0) {
        // causal fast path: out row b = v row (b & 127)
        const float4* v4 = reinterpret_cast<const float4*>(v)
                           + (size_t)(b & 127) * ROW4;
        stcs4(out4 + tid, __ldg(v4 + tid));
        return;
    }

    // ---- non-causal fallback (never exercised by setup_inputs) ----
    // Row r = b. seg = r>>7, qi = r&127, key positions pos_j = qi + step*j.
    // 8 warps x 2 heads/warp; warp-cooperative softmax-attention, 128 keys, D=64.
    const int r    = b;
    const int qi   = r & 127;
    const int step = 128 << (r >> 7);       // 128 or 256
    const int wid  = tid >> 5;
    const int lane = tid & 31;
    const float scale = 0.125f;             // 1/sqrt(64)

    #pragma unroll
    for (int hh = 0; hh < 2; hh++) {
        const int h = wid * 2 + hh;
        const float* qp = q + (size_t)r * HD + h * 64;
        const float q0 = qp[lane];
        const float q1 = qp[lane + 32];

        // distributed scores: lane l keeps score j where (j & 31) == l
        float sc[4];
        for (int j = 0; j < 128; j++) {
            const int pos = qi + step * j;
            const float* kp = k + (size_t)pos * HD + h * 64;
            float p = q0 * kp[lane] + q1 * kp[lane + 32];
            #pragma unroll
            for (int off = 16; off >= 1; off >>= 1)
                p += __shfl_xor_sync(0xFFFFFFFFu, p, off);
            if ((j & 31) == lane) sc[j >> 5] = p * scale;
        }

        float m = fmaxf(fmaxf(sc[0], sc[1]), fmaxf(sc[2], sc[3]));
        #pragma unroll
        for (int off = 16; off >= 1; off >>= 1)
            m = fmaxf(m, __shfl_xor_sync(0xFFFFFFFFu, m, off));
        float e[4], lsum = 0.f;
        #pragma unroll
        for (int jj = 0; jj < 4; jj++) { e[jj] = __expf(sc[jj] - m); lsum += e[jj]; }
        #pragma unroll
        for (int off = 16; off >= 1; off >>= 1)
            lsum += __shfl_xor_sync(0xFFFFFFFFu, lsum, off);
        const float inv = 1.f / lsum;

        float acc0 = 0.f, acc1 = 0.f;
        for (int j = 0; j < 128; j++) {
            const float w = __shfl_sync(0xFFFFFFFFu, e[j >> 5], j & 31) * inv;
            const int pos = qi + step * j;
            const float* vp = v + (size_t)pos * HD + h * 64;
            acc0 += w * vp[lane];
            acc1 += w * vp[lane + 32];
        }

        float* op = out + (size_t)r * HD + h * 64;
        op[lane]      = acc0;
        op[lane + 32] = acc1;
    }
}

extern "C" void kernel_launch(void* const* d_in, const int* in_sizes, int n_in,
                              void* d_out, int out_size)
{
    const float* q = (const float*)d_in[0];
    const float* k = (const float*)d_in[1];
    const float* v = (const float*)d_in[2];
    const int* is_causal = (const int*)d_in[3];
    float* out = (float*)d_out;

    fused_dilated_attn_kernel<<<GRID, 256>>>(q, k, v, is_causal, out);
}